// round 1
// baseline (speedup 1.0000x reference)
#include <cuda_runtime.h>
#include <math.h>

// Problem constants (fixed by the reference)
#define NB     4
#define SEQ    2048
#define DMODEL 512
#define NH     8
#define DKH    64
#define FDIM   2048
#define MROWS  (NB*SEQ)   // 8192

// -------- scratch (device globals; no allocation allowed) --------
__device__ float g_h  [MROWS*DMODEL];
__device__ float g_q  [MROWS*DMODEL];
__device__ float g_k  [MROWS*DMODEL];
__device__ float g_v  [MROWS*DMODEL];
__device__ float g_ctx[MROWS*DMODEL];
__device__ float g_x1 [MROWS*DMODEL];
__device__ float g_h2 [MROWS*DMODEL];
__device__ float g_ff [MROWS*FDIM];

// ----------------- LayerNorm (torch semantics) -----------------
// row of 512, 128 threads, 4 floats/thread
__global__ __launch_bounds__(128) void ln_k(const float* __restrict__ x,
                                            float* __restrict__ out,
                                            const float* __restrict__ alpha,
                                            const float* __restrict__ beta) {
    __shared__ float red[4];
    int row = blockIdx.x;
    const float4* xr = (const float4*)(x + (size_t)row * DMODEL);
    float4 v = xr[threadIdx.x];
    float s = v.x + v.y + v.z + v.w;
    #pragma unroll
    for (int o = 16; o; o >>= 1) s += __shfl_xor_sync(0xffffffffu, s, o);
    if ((threadIdx.x & 31) == 0) red[threadIdx.x >> 5] = s;
    __syncthreads();
    s = red[0] + red[1] + red[2] + red[3];
    float mean = s * (1.f / DMODEL);
    float dx = v.x - mean, dy = v.y - mean, dz = v.z - mean, dw = v.w - mean;
    float ss = dx*dx + dy*dy + dz*dz + dw*dw;
    #pragma unroll
    for (int o = 16; o; o >>= 1) ss += __shfl_xor_sync(0xffffffffu, ss, o);
    __syncthreads();
    if ((threadIdx.x & 31) == 0) red[threadIdx.x >> 5] = ss;
    __syncthreads();
    ss = red[0] + red[1] + red[2] + red[3];
    float var = ss * (1.f / (DMODEL - 1));            // Bessel-corrected
    float inv = 1.f / (sqrtf(var) + 1e-6f);           // eps on std, not var
    float a = alpha[0], b = beta[0];
    float4 o4;
    o4.x = a * dx * inv + b;
    o4.y = a * dy * inv + b;
    o4.z = a * dz * inv + b;
    o4.w = a * dw * inv + b;
    ((float4*)(out + (size_t)row * DMODEL))[threadIdx.x] = o4;
}

// ----------------- SGEMM NT: C[M,N] = A[M,K] * B[N,K]^T + bias (+res)(relu) -----------------
// 128x128 tile, BK=8, 256 threads, 8x8 per thread
template<int RELU, int RES>
__global__ __launch_bounds__(256) void gemm_nt(const float* __restrict__ A,
                                               const float* __restrict__ B,
                                               const float* __restrict__ bias,
                                               const float* __restrict__ res,
                                               float* __restrict__ C,
                                               int M, int N, int K) {
    __shared__ float As[8][128];
    __shared__ float Bs[8][128];
    int tid = threadIdx.x;
    int bm = blockIdx.y * 128, bn = blockIdx.x * 128;
    int lrow = tid >> 1;
    int lcol = (tid & 1) * 4;
    const float* Ag = A + (size_t)(bm + lrow) * K + lcol;
    const float* Bg = B + (size_t)(bn + lrow) * K + lcol;
    int tx = tid & 15, ty = tid >> 4;

    float acc[8][8];
    #pragma unroll
    for (int i = 0; i < 8; i++)
        #pragma unroll
        for (int j = 0; j < 8; j++) acc[i][j] = 0.f;

    for (int kt = 0; kt < K; kt += 8) {
        float4 av = *(const float4*)(Ag + kt);
        float4 bv = *(const float4*)(Bg + kt);
        __syncthreads();   // previous iteration's compute done
        As[lcol + 0][lrow] = av.x; As[lcol + 1][lrow] = av.y;
        As[lcol + 2][lrow] = av.z; As[lcol + 3][lrow] = av.w;
        Bs[lcol + 0][lrow] = bv.x; Bs[lcol + 1][lrow] = bv.y;
        Bs[lcol + 2][lrow] = bv.z; Bs[lcol + 3][lrow] = bv.w;
        __syncthreads();
        #pragma unroll
        for (int k = 0; k < 8; k++) {
            float4 a0 = *(const float4*)&As[k][ty * 8];
            float4 a1 = *(const float4*)&As[k][ty * 8 + 4];
            float4 b0 = *(const float4*)&Bs[k][tx * 8];
            float4 b1 = *(const float4*)&Bs[k][tx * 8 + 4];
            float af[8] = {a0.x, a0.y, a0.z, a0.w, a1.x, a1.y, a1.z, a1.w};
            float bf[8] = {b0.x, b0.y, b0.z, b0.w, b1.x, b1.y, b1.z, b1.w};
            #pragma unroll
            for (int i = 0; i < 8; i++)
                #pragma unroll
                for (int j = 0; j < 8; j++)
                    acc[i][j] += af[i] * bf[j];
        }
    }

    #pragma unroll
    for (int i = 0; i < 8; i++) {
        int row = bm + ty * 8 + i;
        #pragma unroll
        for (int j = 0; j < 8; j += 4) {
            int col = bn + tx * 8 + j;
            float4 r;
            r.x = acc[i][j + 0] + bias[col + 0];
            r.y = acc[i][j + 1] + bias[col + 1];
            r.z = acc[i][j + 2] + bias[col + 2];
            r.w = acc[i][j + 3] + bias[col + 3];
            if (RELU) {
                r.x = fmaxf(r.x, 0.f); r.y = fmaxf(r.y, 0.f);
                r.z = fmaxf(r.z, 0.f); r.w = fmaxf(r.w, 0.f);
            }
            if (RES) {
                float4 rv = *(const float4*)&res[(size_t)row * N + col];
                r.x += rv.x; r.y += rv.y; r.z += rv.z; r.w += rv.w;
            }
            *(float4*)&C[(size_t)row * N + col] = r;
        }
    }
}

// ----------------- Flash attention, fp32, 1 query row / thread -----------------
__global__ __launch_bounds__(128) void attn_k(const float* __restrict__ Q,
                                              const float* __restrict__ K,
                                              const float* __restrict__ V,
                                              const int* __restrict__ mask,
                                              float* __restrict__ O) {
    __shared__ float Ks[16][64];
    __shared__ float Vs[16][64];
    __shared__ float madd[16];
    int bh = blockIdx.x;
    int b = bh >> 3, hh = bh & 7;
    int srow = blockIdx.y * 128 + threadIdx.x;
    size_t m = (size_t)b * SEQ + srow;

    const float* qp = Q + m * DMODEL + hh * DKH;
    float qr[64];
    #pragma unroll
    for (int i = 0; i < 16; i++) {
        float4 t = *(const float4*)(qp + i * 4);
        qr[4*i+0] = t.x * 0.125f; qr[4*i+1] = t.y * 0.125f;
        qr[4*i+2] = t.z * 0.125f; qr[4*i+3] = t.w * 0.125f;
    }
    float acc[64];
    #pragma unroll
    for (int i = 0; i < 64; i++) acc[i] = 0.f;
    float mrun = -1e30f, l = 0.f;

    int lr = threadIdx.x >> 3;          // 0..15 key row in tile
    int lc = (threadIdx.x & 7) * 8;     // 0..56 col
    const float* kb = K + (size_t)b * SEQ * DMODEL + hh * DKH;
    const float* vb = V + (size_t)b * SEQ * DMODEL + hh * DKH;

    for (int kt = 0; kt < SEQ; kt += 16) {
        const float* kp = kb + (size_t)(kt + lr) * DMODEL + lc;
        const float* vp = vb + (size_t)(kt + lr) * DMODEL + lc;
        float4 k0 = *(const float4*)kp, k1 = *(const float4*)(kp + 4);
        float4 v0 = *(const float4*)vp, v1 = *(const float4*)(vp + 4);
        *(float4*)&Ks[lr][lc]     = k0; *(float4*)&Ks[lr][lc + 4] = k1;
        *(float4*)&Vs[lr][lc]     = v0; *(float4*)&Vs[lr][lc + 4] = v1;
        if (threadIdx.x < 16)
            madd[threadIdx.x] = (mask[b * SEQ + kt + threadIdx.x] == 0) ? -1e9f : 0.f;
        __syncthreads();

        float s[16]; float smax = -1e30f;
        #pragma unroll
        for (int j = 0; j < 16; j++) {
            float p0 = 0.f, p1 = 0.f, p2 = 0.f, p3 = 0.f;
            #pragma unroll
            for (int d = 0; d < 64; d += 4) {
                p0 += qr[d+0] * Ks[j][d+0];
                p1 += qr[d+1] * Ks[j][d+1];
                p2 += qr[d+2] * Ks[j][d+2];
                p3 += qr[d+3] * Ks[j][d+3];
            }
            float sv = (p0 + p1) + (p2 + p3) + madd[j];
            s[j] = sv;
            smax = fmaxf(smax, sv);
        }
        float mnew = fmaxf(mrun, smax);
        float corr = __expf(mrun - mnew);   // exp(-inf)=0 on first tile
        l *= corr;
        #pragma unroll
        for (int d = 0; d < 64; d++) acc[d] *= corr;
        #pragma unroll
        for (int j = 0; j < 16; j++) {
            float p = __expf(s[j] - mnew);
            l += p;
            #pragma unroll
            for (int d = 0; d < 64; d++) acc[d] += p * Vs[j][d];
        }
        mrun = mnew;
        __syncthreads();
    }

    float invl = 1.f / l;
    float* op = O + m * DMODEL + hh * DKH;
    #pragma unroll
    for (int i = 0; i < 16; i++) {
        float4 t;
        t.x = acc[4*i+0] * invl; t.y = acc[4*i+1] * invl;
        t.z = acc[4*i+2] * invl; t.w = acc[4*i+3] * invl;
        *(float4*)(op + i * 4) = t;
    }
}

// ----------------- launch -----------------
extern "C" void kernel_launch(void* const* d_in, const int* in_sizes, int n_in,
                              void* d_out, int out_size) {
    const float* x    = (const float*)d_in[0];
    const int*   mask = (const int*)  d_in[1];
    const float* wq = (const float*)d_in[2];  const float* bq = (const float*)d_in[3];
    const float* wk = (const float*)d_in[4];  const float* bk = (const float*)d_in[5];
    const float* wv = (const float*)d_in[6];  const float* bv = (const float*)d_in[7];
    const float* wo = (const float*)d_in[8];  const float* bo = (const float*)d_in[9];
    const float* w1 = (const float*)d_in[10]; const float* b1 = (const float*)d_in[11];
    const float* w2 = (const float*)d_in[12]; const float* b2 = (const float*)d_in[13];
    const float* a1 = (const float*)d_in[14]; const float* g1 = (const float*)d_in[15];
    const float* a2 = (const float*)d_in[16]; const float* g2 = (const float*)d_in[17];
    float* out = (float*)d_out;

    float *h, *q, *k, *v, *ctx, *x1, *h2, *ff;
    cudaGetSymbolAddress((void**)&h,   g_h);
    cudaGetSymbolAddress((void**)&q,   g_q);
    cudaGetSymbolAddress((void**)&k,   g_k);
    cudaGetSymbolAddress((void**)&v,   g_v);
    cudaGetSymbolAddress((void**)&ctx, g_ctx);
    cudaGetSymbolAddress((void**)&x1,  g_x1);
    cudaGetSymbolAddress((void**)&h2,  g_h2);
    cudaGetSymbolAddress((void**)&ff,  g_ff);

    // LN1
    ln_k<<<MROWS, 128>>>(x, h, a1, g1);

    // QKV projections
    dim3 gp(DMODEL / 128, MROWS / 128);
    gemm_nt<0,0><<<gp, 256>>>(h, wq, bq, nullptr, q, MROWS, DMODEL, DMODEL);
    gemm_nt<0,0><<<gp, 256>>>(h, wk, bk, nullptr, k, MROWS, DMODEL, DMODEL);
    gemm_nt<0,0><<<gp, 256>>>(h, wv, bv, nullptr, v, MROWS, DMODEL, DMODEL);

    // attention
    dim3 ga(NB * NH, SEQ / 128);
    attn_k<<<ga, 128>>>(q, k, v, mask, ctx);

    // output projection + residual
    gemm_nt<0,1><<<gp, 256>>>(ctx, wo, bo, x, x1, MROWS, DMODEL, DMODEL);

    // LN2
    ln_k<<<MROWS, 128>>>(x1, h2, a2, g2);

    // FFN
    dim3 gf1(FDIM / 128, MROWS / 128);
    gemm_nt<1,0><<<gf1, 256>>>(h2, w1, b1, nullptr, ff, MROWS, FDIM, DMODEL);
    gemm_nt<0,1><<<gp, 256>>>(ff, w2, b2, x1, out, MROWS, DMODEL, FDIM);
}

// round 3
// speedup vs baseline: 1.4141x; 1.4141x over previous
#include <cuda_runtime.h>
#include <math.h>
#include <stdint.h>

// Problem constants (fixed by the reference)
#define NB     4
#define SEQ    2048
#define DMODEL 512
#define NH     8
#define DKH    64
#define FDIM   2048
#define MROWS  (NB*SEQ)   // 8192

// -------- scratch (device globals; no allocation allowed) --------
__device__ float g_h  [MROWS*DMODEL];
__device__ float g_q  [MROWS*DMODEL];
__device__ float g_k  [MROWS*DMODEL];
__device__ float g_v  [MROWS*DMODEL];
__device__ float g_ctx[MROWS*DMODEL];
__device__ float g_x1 [MROWS*DMODEL];
__device__ float g_h2 [MROWS*DMODEL];
__device__ float g_ff [MROWS*FDIM];

// ================= helpers =================
__device__ __forceinline__ uint32_t smem_u32(const void* p) {
    uint32_t a;
    asm("{ .reg .u64 t; cvta.to.shared.u64 t, %1; cvt.u32.u64 %0, t; }" : "=r"(a) : "l"(p));
    return a;
}
__device__ __forceinline__ void cp16(uint32_t dst, const void* src) {
    asm volatile("cp.async.cg.shared.global [%0], [%1], 16;" :: "r"(dst), "l"(src) : "memory");
}
__device__ __forceinline__ uint32_t f2tf(float f) {
    uint32_t r; asm("cvt.rna.tf32.f32 %0, %1;" : "=r"(r) : "f"(f)); return r;
}
__device__ __forceinline__ void mma_tf32(float* c, const uint32_t* a, const uint32_t* b) {
    asm volatile("mma.sync.aligned.m16n8k8.row.col.f32.tf32.tf32.f32 "
        "{%0,%1,%2,%3}, {%4,%5,%6,%7}, {%8,%9}, {%0,%1,%2,%3};"
        : "+f"(c[0]), "+f"(c[1]), "+f"(c[2]), "+f"(c[3])
        : "r"(a[0]), "r"(a[1]), "r"(a[2]), "r"(a[3]), "r"(b[0]), "r"(b[1]));
}

// ================= LayerNorm (torch semantics) =================
__global__ __launch_bounds__(128) void ln_k(const float* __restrict__ x,
                                            float* __restrict__ out,
                                            const float* __restrict__ alpha,
                                            const float* __restrict__ beta) {
    __shared__ float red[4];
    int row = blockIdx.x;
    const float4* xr = (const float4*)(x + (size_t)row * DMODEL);
    float4 v = xr[threadIdx.x];
    float s = v.x + v.y + v.z + v.w;
    #pragma unroll
    for (int o = 16; o; o >>= 1) s += __shfl_xor_sync(0xffffffffu, s, o);
    if ((threadIdx.x & 31) == 0) red[threadIdx.x >> 5] = s;
    __syncthreads();
    s = red[0] + red[1] + red[2] + red[3];
    float mean = s * (1.f / DMODEL);
    float dx = v.x - mean, dy = v.y - mean, dz = v.z - mean, dw = v.w - mean;
    float ss = dx*dx + dy*dy + dz*dz + dw*dw;
    #pragma unroll
    for (int o = 16; o; o >>= 1) ss += __shfl_xor_sync(0xffffffffu, ss, o);
    __syncthreads();
    if ((threadIdx.x & 31) == 0) red[threadIdx.x >> 5] = ss;
    __syncthreads();
    ss = red[0] + red[1] + red[2] + red[3];
    float var = ss * (1.f / (DMODEL - 1));            // Bessel-corrected
    float inv = 1.f / (sqrtf(var) + 1e-6f);           // eps on std, not var
    float a = alpha[0], b = beta[0];
    float4 o4;
    o4.x = a * dx * inv + b;
    o4.y = a * dy * inv + b;
    o4.z = a * dz * inv + b;
    o4.w = a * dw * inv + b;
    ((float4*)(out + (size_t)row * DMODEL))[threadIdx.x] = o4;
}

// ================= tf32 warp-MMA GEMM =================
// C[M,N] = A[M,K] * B[N,K]^T + bias (+res)(relu)
// 128x128 CTA tile, BK=32, 8 warps (2x4), warp tile 64x32, m16n8k8 tf32.
// Smem rows padded to 36 floats (144B, 16B-aligned, conflict-free fragment LDS).
#define GROW 36
#define ATILE_B (128 * GROW * 4)            // 18432
#define STAGE_B (2 * ATILE_B)               // 36864 (A + B)
#define GEMM_SMEM (2 * STAGE_B)             // 73728

template<int RELU, int RES>
__global__ __launch_bounds__(256) void gemm_mma(const float* __restrict__ A,
                                                const float* __restrict__ B,
                                                const float* __restrict__ bias,
                                                const float* __restrict__ res,
                                                float* __restrict__ C,
                                                int M, int N, int K) {
    extern __shared__ char smem[];
    uint32_t sb = smem_u32(smem);
    int tid = threadIdx.x, wid = tid >> 5, lane = tid & 31;
    int gr = lane >> 2, gc = lane & 3;
    int wm = (wid >> 2) * 64, wn = (wid & 3) * 32;
    int bm = blockIdx.y * 128, bn = blockIdx.x * 128;

    const float* Abase = A + (size_t)bm * K;
    const float* Bbase = B + (size_t)bn * K;

    float acc[4][4][4];
    #pragma unroll
    for (int i = 0; i < 4; i++)
        #pragma unroll
        for (int j = 0; j < 4; j++)
            #pragma unroll
            for (int r = 0; r < 4; r++) acc[i][j][r] = 0.f;

    int lrow = tid >> 3, lc4 = tid & 7;   // global-load mapping: 4 rows per pass

    auto load_chunk = [&](int c, int s) {
        uint32_t ab = sb + s * STAGE_B;
        uint32_t bb = ab + ATILE_B;
        const float* Ap = Abase + c * 32;
        const float* Bp = Bbase + c * 32;
        #pragma unroll
        for (int i = 0; i < 4; i++) {
            int row = i * 32 + lrow;
            uint32_t off = (uint32_t)(row * (GROW * 4) + lc4 * 16);
            cp16(ab + off, Ap + (size_t)row * K + lc4 * 4);
            cp16(bb + off, Bp + (size_t)row * K + lc4 * 4);
        }
    };

    const int NC = K / 32;
    load_chunk(0, 0);
    asm volatile("cp.async.commit_group;" ::: "memory");
    asm volatile("cp.async.wait_group 0;" ::: "memory");
    __syncthreads();

    int buf = 0;
    for (int ch = 0; ch < NC; ch++) {
        if (ch + 1 < NC) {
            load_chunk(ch + 1, buf ^ 1);
            asm volatile("cp.async.commit_group;" ::: "memory");
        }
        const float* As_ = (const float*)(smem + buf * STAGE_B);
        const float* Bs_ = (const float*)(smem + buf * STAGE_B + ATILE_B);
        #pragma unroll
        for (int ks = 0; ks < 4; ks++) {
            int acol = ks * 8 + gc;
            uint32_t ar[4][4];
            #pragma unroll
            for (int i = 0; i < 4; i++) {
                int r0 = wm + i * 16 + gr;
                ar[i][0] = f2tf(As_[r0 * GROW + acol]);
                ar[i][1] = f2tf(As_[(r0 + 8) * GROW + acol]);
                ar[i][2] = f2tf(As_[r0 * GROW + acol + 4]);
                ar[i][3] = f2tf(As_[(r0 + 8) * GROW + acol + 4]);
            }
            uint32_t br[4][2];
            #pragma unroll
            for (int j = 0; j < 4; j++) {
                int n0 = wn + j * 8 + gr;
                br[j][0] = f2tf(Bs_[n0 * GROW + ks * 8 + gc]);
                br[j][1] = f2tf(Bs_[n0 * GROW + ks * 8 + gc + 4]);
            }
            #pragma unroll
            for (int i = 0; i < 4; i++)
                #pragma unroll
                for (int j = 0; j < 4; j++)
                    mma_tf32(acc[i][j], ar[i], br[j]);
        }
        if (ch + 1 < NC)
            asm volatile("cp.async.wait_group 0;" ::: "memory");
        __syncthreads();
        buf ^= 1;
    }

    // ---- epilogue: registers -> global, fused bias/relu/residual ----
    #pragma unroll
    for (int i = 0; i < 4; i++) {
        int row0 = bm + wm + i * 16 + gr;
        #pragma unroll
        for (int j = 0; j < 4; j++) {
            int col = bn + wn + j * 8 + 2 * gc;
            float2 b2 = *(const float2*)&bias[col];
            float2 v0, v1;
            v0.x = acc[i][j][0] + b2.x; v0.y = acc[i][j][1] + b2.y;
            v1.x = acc[i][j][2] + b2.x; v1.y = acc[i][j][3] + b2.y;
            if (RELU) {
                v0.x = fmaxf(v0.x, 0.f); v0.y = fmaxf(v0.y, 0.f);
                v1.x = fmaxf(v1.x, 0.f); v1.y = fmaxf(v1.y, 0.f);
            }
            if (RES) {
                float2 r0 = *(const float2*)&res[(size_t)row0 * N + col];
                float2 r1 = *(const float2*)&res[(size_t)(row0 + 8) * N + col];
                v0.x += r0.x; v0.y += r0.y;
                v1.x += r1.x; v1.y += r1.y;
            }
            *(float2*)&C[(size_t)row0 * N + col] = v0;
            *(float2*)&C[(size_t)(row0 + 8) * N + col] = v1;
        }
    }
}

// ================= Flash attention, fp32, 1 query row / thread =================
__global__ __launch_bounds__(128) void attn_k(const float* __restrict__ Q,
                                              const float* __restrict__ K,
                                              const float* __restrict__ V,
                                              const int* __restrict__ mask,
                                              float* __restrict__ O) {
    __shared__ float Ks[16][64];
    __shared__ float Vs[16][64];
    __shared__ float madd[16];
    int bh = blockIdx.x;
    int b = bh >> 3, hh = bh & 7;
    int srow = blockIdx.y * 128 + threadIdx.x;
    size_t m = (size_t)b * SEQ + srow;

    const float* qp = Q + m * DMODEL + hh * DKH;
    float qr[64];
    #pragma unroll
    for (int i = 0; i < 16; i++) {
        float4 t = *(const float4*)(qp + i * 4);
        qr[4*i+0] = t.x * 0.125f; qr[4*i+1] = t.y * 0.125f;
        qr[4*i+2] = t.z * 0.125f; qr[4*i+3] = t.w * 0.125f;
    }
    float acc[64];
    #pragma unroll
    for (int i = 0; i < 64; i++) acc[i] = 0.f;
    float mrun = -1e30f, l = 0.f;

    int lr = threadIdx.x >> 3;
    int lc = (threadIdx.x & 7) * 8;
    const float* kb = K + (size_t)b * SEQ * DMODEL + hh * DKH;
    const float* vb = V + (size_t)b * SEQ * DMODEL + hh * DKH;

    for (int kt = 0; kt < SEQ; kt += 16) {
        const float* kp = kb + (size_t)(kt + lr) * DMODEL + lc;
        const float* vp = vb + (size_t)(kt + lr) * DMODEL + lc;
        float4 k0 = *(const float4*)kp, k1 = *(const float4*)(kp + 4);
        float4 v0 = *(const float4*)vp, v1 = *(const float4*)(vp + 4);
        *(float4*)&Ks[lr][lc]     = k0; *(float4*)&Ks[lr][lc + 4] = k1;
        *(float4*)&Vs[lr][lc]     = v0; *(float4*)&Vs[lr][lc + 4] = v1;
        if (threadIdx.x < 16)
            madd[threadIdx.x] = (mask[b * SEQ + kt + threadIdx.x] == 0) ? -1e9f : 0.f;
        __syncthreads();

        float s[16]; float smax = -1e30f;
        #pragma unroll
        for (int j = 0; j < 16; j++) {
            float p0 = 0.f, p1 = 0.f, p2 = 0.f, p3 = 0.f;
            #pragma unroll
            for (int d = 0; d < 64; d += 4) {
                p0 += qr[d+0] * Ks[j][d+0];
                p1 += qr[d+1] * Ks[j][d+1];
                p2 += qr[d+2] * Ks[j][d+2];
                p3 += qr[d+3] * Ks[j][d+3];
            }
            float sv = (p0 + p1) + (p2 + p3) + madd[j];
            s[j] = sv;
            smax = fmaxf(smax, sv);
        }
        float mnew = fmaxf(mrun, smax);
        float corr = __expf(mrun - mnew);
        l *= corr;
        #pragma unroll
        for (int d = 0; d < 64; d++) acc[d] *= corr;
        #pragma unroll
        for (int j = 0; j < 16; j++) {
            float p = __expf(s[j] - mnew);
            l += p;
            #pragma unroll
            for (int d = 0; d < 64; d++) acc[d] += p * Vs[j][d];
        }
        mrun = mnew;
        __syncthreads();
    }

    float invl = 1.f / l;
    float* op = O + m * DMODEL + hh * DKH;
    #pragma unroll
    for (int i = 0; i < 16; i++) {
        float4 t;
        t.x = acc[4*i+0] * invl; t.y = acc[4*i+1] * invl;
        t.z = acc[4*i+2] * invl; t.w = acc[4*i+3] * invl;
        *(float4*)(op + i * 4) = t;
    }
}

// ================= launch =================
extern "C" void kernel_launch(void* const* d_in, const int* in_sizes, int n_in,
                              void* d_out, int out_size) {
    const float* x    = (const float*)d_in[0];
    const int*   mask = (const int*)  d_in[1];
    const float* wq = (const float*)d_in[2];  const float* bq = (const float*)d_in[3];
    const float* wk = (const float*)d_in[4];  const float* bk = (const float*)d_in[5];
    const float* wv = (const float*)d_in[6];  const float* bv = (const float*)d_in[7];
    const float* wo = (const float*)d_in[8];  const float* bo = (const float*)d_in[9];
    const float* w1 = (const float*)d_in[10]; const float* b1 = (const float*)d_in[11];
    const float* w2 = (const float*)d_in[12]; const float* b2 = (const float*)d_in[13];
    const float* a1 = (const float*)d_in[14]; const float* g1 = (const float*)d_in[15];
    const float* a2 = (const float*)d_in[16]; const float* g2 = (const float*)d_in[17];
    float* out = (float*)d_out;

    float *h, *q, *k, *v, *ctx, *x1, *h2, *ff;
    cudaGetSymbolAddress((void**)&h,   g_h);
    cudaGetSymbolAddress((void**)&q,   g_q);
    cudaGetSymbolAddress((void**)&k,   g_k);
    cudaGetSymbolAddress((void**)&v,   g_v);
    cudaGetSymbolAddress((void**)&ctx, g_ctx);
    cudaGetSymbolAddress((void**)&x1,  g_x1);
    cudaGetSymbolAddress((void**)&h2,  g_h2);
    cudaGetSymbolAddress((void**)&ff,  g_ff);

    cudaFuncSetAttribute(gemm_mma<0,0>, cudaFuncAttributeMaxDynamicSharedMemorySize, GEMM_SMEM);
    cudaFuncSetAttribute(gemm_mma<0,1>, cudaFuncAttributeMaxDynamicSharedMemorySize, GEMM_SMEM);
    cudaFuncSetAttribute(gemm_mma<1,0>, cudaFuncAttributeMaxDynamicSharedMemorySize, GEMM_SMEM);

    // LN1
    ln_k<<<MROWS, 128>>>(x, h, a1, g1);

    // QKV projections
    dim3 gp(DMODEL / 128, MROWS / 128);
    gemm_mma<0,0><<<gp, 256, GEMM_SMEM>>>(h, wq, bq, nullptr, q, MROWS, DMODEL, DMODEL);
    gemm_mma<0,0><<<gp, 256, GEMM_SMEM>>>(h, wk, bk, nullptr, k, MROWS, DMODEL, DMODEL);
    gemm_mma<0,0><<<gp, 256, GEMM_SMEM>>>(h, wv, bv, nullptr, v, MROWS, DMODEL, DMODEL);

    // attention
    dim3 ga(NB * NH, SEQ / 128);
    attn_k<<<ga, 128>>>(q, k, v, mask, ctx);

    // output projection + residual
    gemm_mma<0,1><<<gp, 256, GEMM_SMEM>>>(ctx, wo, bo, x, x1, MROWS, DMODEL, DMODEL);

    // LN2
    ln_k<<<MROWS, 128>>>(x1, h2, a2, g2);

    // FFN
    dim3 gf1(FDIM / 128, MROWS / 128);
    gemm_mma<1,0><<<gf1, 256, GEMM_SMEM>>>(h2, w1, b1, nullptr, ff, MROWS, FDIM, DMODEL);
    gemm_mma<0,1><<<gp, 256, GEMM_SMEM>>>(ff, w2, b2, x1, out, MROWS, DMODEL, FDIM);
}

// round 5
// speedup vs baseline: 3.5315x; 2.4974x over previous
#include <cuda_runtime.h>
#include <math.h>
#include <stdint.h>

#define NB     4
#define SEQ    2048
#define DMODEL 512
#define NH     8
#define DKH    64
#define FDIM   2048
#define MROWS  (NB*SEQ)   // 8192

// -------- scratch (device globals; no allocation allowed) --------
__device__ float g_h  [MROWS*DMODEL];
__device__ float g_q  [MROWS*DMODEL];
__device__ float g_k  [MROWS*DMODEL];
__device__ float g_v  [MROWS*DMODEL];
__device__ float g_ctx[MROWS*DMODEL];
__device__ float g_x1 [MROWS*DMODEL];
__device__ float g_h2 [MROWS*DMODEL];
__device__ float g_ff [MROWS*FDIM];

// ================= helpers =================
__device__ __forceinline__ uint32_t smem_u32(const void* p) {
    uint32_t a;
    asm("{ .reg .u64 t; cvta.to.shared.u64 t, %1; cvt.u32.u64 %0, t; }" : "=r"(a) : "l"(p));
    return a;
}
__device__ __forceinline__ void cp16(uint32_t dst, const void* src) {
    asm volatile("cp.async.cg.shared.global [%0], [%1], 16;" :: "r"(dst), "l"(src) : "memory");
}
__device__ __forceinline__ uint32_t f2tf(float f) {
    uint32_t r; asm("cvt.rna.tf32.f32 %0, %1;" : "=r"(r) : "f"(f)); return r;
}
__device__ __forceinline__ void mma_tf32(float* c, const uint32_t* a, const uint32_t* b) {
    asm volatile("mma.sync.aligned.m16n8k8.row.col.f32.tf32.tf32.f32 "
        "{%0,%1,%2,%3}, {%4,%5,%6,%7}, {%8,%9}, {%0,%1,%2,%3};"
        : "+f"(c[0]), "+f"(c[1]), "+f"(c[2]), "+f"(c[3])
        : "r"(a[0]), "r"(a[1]), "r"(a[2]), "r"(a[3]), "r"(b[0]), "r"(b[1]));
}

// ================= LayerNorm (torch semantics) =================
__global__ __launch_bounds__(128) void ln_k(const float* __restrict__ x,
                                            float* __restrict__ out,
                                            const float* __restrict__ alpha,
                                            const float* __restrict__ beta) {
    __shared__ float red[4];
    int row = blockIdx.x;
    const float4* xr = (const float4*)(x + (size_t)row * DMODEL);
    float4 v = xr[threadIdx.x];
    float s = v.x + v.y + v.z + v.w;
    #pragma unroll
    for (int o = 16; o; o >>= 1) s += __shfl_xor_sync(0xffffffffu, s, o);
    if ((threadIdx.x & 31) == 0) red[threadIdx.x >> 5] = s;
    __syncthreads();
    s = red[0] + red[1] + red[2] + red[3];
    float mean = s * (1.f / DMODEL);
    float dx = v.x - mean, dy = v.y - mean, dz = v.z - mean, dw = v.w - mean;
    float ss = dx*dx + dy*dy + dz*dz + dw*dw;
    #pragma unroll
    for (int o = 16; o; o >>= 1) ss += __shfl_xor_sync(0xffffffffu, ss, o);
    __syncthreads();
    if ((threadIdx.x & 31) == 0) red[threadIdx.x >> 5] = ss;
    __syncthreads();
    ss = red[0] + red[1] + red[2] + red[3];
    float var = ss * (1.f / (DMODEL - 1));
    float inv = 1.f / (sqrtf(var) + 1e-6f);
    float a = alpha[0], b = beta[0];
    float4 o4;
    o4.x = a * dx * inv + b;
    o4.y = a * dy * inv + b;
    o4.z = a * dz * inv + b;
    o4.w = a * dw * inv + b;
    ((float4*)(out + (size_t)row * DMODEL))[threadIdx.x] = o4;
}

// ================= tf32 warp-MMA GEMM (unchanged, proven) =================
#define GROW 36
#define ATILE_B (128 * GROW * 4)
#define STAGE_B (2 * ATILE_B)
#define GEMM_SMEM (2 * STAGE_B)

template<int RELU, int RES>
__global__ __launch_bounds__(256) void gemm_mma(const float* __restrict__ A,
                                                const float* __restrict__ B,
                                                const float* __restrict__ bias,
                                                const float* __restrict__ res,
                                                float* __restrict__ C,
                                                int M, int N, int K) {
    extern __shared__ char smem[];
    uint32_t sb = smem_u32(smem);
    int tid = threadIdx.x, wid = tid >> 5, lane = tid & 31;
    int gr = lane >> 2, gc = lane & 3;
    int wm = (wid >> 2) * 64, wn = (wid & 3) * 32;
    int bm = blockIdx.y * 128, bn = blockIdx.x * 128;

    const float* Abase = A + (size_t)bm * K;
    const float* Bbase = B + (size_t)bn * K;

    float acc[4][4][4];
    #pragma unroll
    for (int i = 0; i < 4; i++)
        #pragma unroll
        for (int j = 0; j < 4; j++)
            #pragma unroll
            for (int r = 0; r < 4; r++) acc[i][j][r] = 0.f;

    int lrow = tid >> 3, lc4 = tid & 7;

    auto load_chunk = [&](int c, int s) {
        uint32_t ab = sb + s * STAGE_B;
        uint32_t bb = ab + ATILE_B;
        const float* Ap = Abase + c * 32;
        const float* Bp = Bbase + c * 32;
        #pragma unroll
        for (int i = 0; i < 4; i++) {
            int row = i * 32 + lrow;
            uint32_t off = (uint32_t)(row * (GROW * 4) + lc4 * 16);
            cp16(ab + off, Ap + (size_t)row * K + lc4 * 4);
            cp16(bb + off, Bp + (size_t)row * K + lc4 * 4);
        }
    };

    const int NC = K / 32;
    load_chunk(0, 0);
    asm volatile("cp.async.commit_group;" ::: "memory");
    asm volatile("cp.async.wait_group 0;" ::: "memory");
    __syncthreads();

    int buf = 0;
    for (int ch = 0; ch < NC; ch++) {
        if (ch + 1 < NC) {
            load_chunk(ch + 1, buf ^ 1);
            asm volatile("cp.async.commit_group;" ::: "memory");
        }
        const float* As_ = (const float*)(smem + buf * STAGE_B);
        const float* Bs_ = (const float*)(smem + buf * STAGE_B + ATILE_B);
        #pragma unroll
        for (int ks = 0; ks < 4; ks++) {
            int acol = ks * 8 + gc;
            uint32_t ar[4][4];
            #pragma unroll
            for (int i = 0; i < 4; i++) {
                int r0 = wm + i * 16 + gr;
                ar[i][0] = f2tf(As_[r0 * GROW + acol]);
                ar[i][1] = f2tf(As_[(r0 + 8) * GROW + acol]);
                ar[i][2] = f2tf(As_[r0 * GROW + acol + 4]);
                ar[i][3] = f2tf(As_[(r0 + 8) * GROW + acol + 4]);
            }
            uint32_t br[4][2];
            #pragma unroll
            for (int j = 0; j < 4; j++) {
                int n0 = wn + j * 8 + gr;
                br[j][0] = f2tf(Bs_[n0 * GROW + ks * 8 + gc]);
                br[j][1] = f2tf(Bs_[n0 * GROW + ks * 8 + gc + 4]);
            }
            #pragma unroll
            for (int i = 0; i < 4; i++)
                #pragma unroll
                for (int j = 0; j < 4; j++)
                    mma_tf32(acc[i][j], ar[i], br[j]);
        }
        if (ch + 1 < NC)
            asm volatile("cp.async.wait_group 0;" ::: "memory");
        __syncthreads();
        buf ^= 1;
    }

    #pragma unroll
    for (int i = 0; i < 4; i++) {
        int row0 = bm + wm + i * 16 + gr;
        #pragma unroll
        for (int j = 0; j < 4; j++) {
            int col = bn + wn + j * 8 + 2 * gc;
            float2 b2 = *(const float2*)&bias[col];
            float2 v0, v1;
            v0.x = acc[i][j][0] + b2.x; v0.y = acc[i][j][1] + b2.y;
            v1.x = acc[i][j][2] + b2.x; v1.y = acc[i][j][3] + b2.y;
            if (RELU) {
                v0.x = fmaxf(v0.x, 0.f); v0.y = fmaxf(v0.y, 0.f);
                v1.x = fmaxf(v1.x, 0.f); v1.y = fmaxf(v1.y, 0.f);
            }
            if (RES) {
                float2 r0 = *(const float2*)&res[(size_t)row0 * N + col];
                float2 r1 = *(const float2*)&res[(size_t)(row0 + 8) * N + col];
                v0.x += r0.x; v0.y += r0.y;
                v1.x += r1.x; v1.y += r1.y;
            }
            *(float2*)&C[(size_t)row0 * N + col] = v0;
            *(float2*)&C[(size_t)(row0 + 8) * N + col] = v1;
        }
    }
}

// ================= tf32 warp-MMA flash attention =================
// CTA: 128 queries x one (b,h). 8 warps x 16 query rows. 64-key tiles.
// Smem: Ks[64][68], VT[64][68] (V transposed), madd[64], Ps[8][16][68]
#define APAD 68
#define AT_KS   0
#define AT_VT   (64 * APAD)
#define AT_MADD (2 * 64 * APAD)
#define AT_PS   (2 * 64 * APAD + 64)
#define ATTN_SMEM ((2 * 64 * APAD + 64 + 8 * 16 * APAD) * 4)

__global__ __launch_bounds__(256, 2) void attn_mma(const float* __restrict__ Q,
                                                   const float* __restrict__ K,
                                                   const float* __restrict__ V,
                                                   const int* __restrict__ mask,
                                                   float* __restrict__ O) {
    extern __shared__ float sm[];
    uint32_t sb = smem_u32(sm);
    float* Ks   = sm + AT_KS;
    float* VT   = sm + AT_VT;
    float* madd = sm + AT_MADD;

    int tid = threadIdx.x, wid = tid >> 5, lane = tid & 31;
    int gr = lane >> 2, gc = lane & 3;
    int bh = blockIdx.x, b = bh >> 3, hh = bh & 7;
    int q0 = blockIdx.y * 128;
    int wrow = wid * 16;

    const float* Qb = Q + ((size_t)b * SEQ + q0) * DMODEL + hh * DKH;
    const float* Kb = K + (size_t)b * SEQ * DMODEL + hh * DKH;
    const float* Vb = V + (size_t)b * SEQ * DMODEL + hh * DKH;
    float* Pw = sm + AT_PS + wid * 16 * APAD;

    // Q fragments, pre-scaled by 1/sqrt(64), pre-converted to tf32
    uint32_t qa[8][4];
    #pragma unroll
    for (int ks = 0; ks < 8; ks++) {
        int r0 = wrow + gr, c0 = ks * 8 + gc;
        qa[ks][0] = f2tf(Qb[(size_t)r0 * DMODEL + c0] * 0.125f);
        qa[ks][1] = f2tf(Qb[(size_t)(r0 + 8) * DMODEL + c0] * 0.125f);
        qa[ks][2] = f2tf(Qb[(size_t)r0 * DMODEL + c0 + 4] * 0.125f);
        qa[ks][3] = f2tf(Qb[(size_t)(r0 + 8) * DMODEL + c0 + 4] * 0.125f);
    }

    float o[8][4];
    #pragma unroll
    for (int j = 0; j < 8; j++)
        #pragma unroll
        for (int r = 0; r < 4; r++) o[j][r] = 0.f;
    float m0 = -1e30f, m1 = -1e30f, l0 = 0.f, l1 = 0.f;

    // V transpose mapping: d = tid&63, key group k4 = (tid>>6)*16
    int vd = tid & 63, vk4 = (tid >> 6) * 16;
    // K cp.async mapping: 1024 float4s
    for (int kt = 0; kt < SEQ; kt += 64) {
        __syncthreads();
        // K tile -> Ks[key][dim]
        #pragma unroll
        for (int i = 0; i < 4; i++) {
            int li = i * 256 + tid;
            int row = li >> 4, c16 = li & 15;
            cp16(sb + (uint32_t)((AT_KS + row * APAD + c16 * 4) * 4),
                 Kb + (size_t)(kt + row) * DMODEL + c16 * 4);
        }
        asm volatile("cp.async.commit_group;" ::: "memory");
        // V tile transposed -> VT[dim][key]
        #pragma unroll
        for (int i = 0; i < 16; i++) {
            VT[vd * APAD + vk4 + i] = __ldg(&Vb[(size_t)(kt + vk4 + i) * DMODEL + vd]);
        }
        if (tid < 64)
            madd[tid] = (mask[b * SEQ + kt + tid] == 0) ? -1e9f : 0.f;
        asm volatile("cp.async.wait_group 0;" ::: "memory");
        __syncthreads();

        // ---- S = Q K^T ----
        float s[8][4];
        #pragma unroll
        for (int j = 0; j < 8; j++)
            #pragma unroll
            for (int r = 0; r < 4; r++) s[j][r] = 0.f;
        #pragma unroll
        for (int ks = 0; ks < 8; ks++) {
            #pragma unroll
            for (int j = 0; j < 8; j++) {
                uint32_t br[2];
                br[0] = f2tf(Ks[(j * 8 + gr) * APAD + ks * 8 + gc]);
                br[1] = f2tf(Ks[(j * 8 + gr) * APAD + ks * 8 + gc + 4]);
                mma_tf32(s[j], qa[ks], br);
            }
        }

        // ---- mask + online softmax ----
        float rmax0 = -1e30f, rmax1 = -1e30f;
        #pragma unroll
        for (int j = 0; j < 8; j++) {
            float md0 = madd[j * 8 + 2 * gc];
            float md1 = madd[j * 8 + 2 * gc + 1];
            s[j][0] += md0; s[j][1] += md1;
            s[j][2] += md0; s[j][3] += md1;
            rmax0 = fmaxf(rmax0, fmaxf(s[j][0], s[j][1]));
            rmax1 = fmaxf(rmax1, fmaxf(s[j][2], s[j][3]));
        }
        #pragma unroll
        for (int off = 1; off <= 2; off <<= 1) {
            rmax0 = fmaxf(rmax0, __shfl_xor_sync(0xffffffffu, rmax0, off));
            rmax1 = fmaxf(rmax1, __shfl_xor_sync(0xffffffffu, rmax1, off));
        }
        float mn0 = fmaxf(m0, rmax0), mn1 = fmaxf(m1, rmax1);
        float cr0 = __expf(m0 - mn0), cr1 = __expf(m1 - mn1);
        float ls0 = 0.f, ls1 = 0.f;
        #pragma unroll
        for (int j = 0; j < 8; j++) {
            s[j][0] = __expf(s[j][0] - mn0);
            s[j][1] = __expf(s[j][1] - mn0);
            s[j][2] = __expf(s[j][2] - mn1);
            s[j][3] = __expf(s[j][3] - mn1);
            ls0 += s[j][0] + s[j][1];
            ls1 += s[j][2] + s[j][3];
        }
        #pragma unroll
        for (int off = 1; off <= 2; off <<= 1) {
            ls0 += __shfl_xor_sync(0xffffffffu, ls0, off);
            ls1 += __shfl_xor_sync(0xffffffffu, ls1, off);
        }
        l0 = l0 * cr0 + ls0;
        l1 = l1 * cr1 + ls1;
        m0 = mn0; m1 = mn1;
        #pragma unroll
        for (int j = 0; j < 8; j++) {
            o[j][0] *= cr0; o[j][1] *= cr0;
            o[j][2] *= cr1; o[j][3] *= cr1;
        }

        // ---- P to per-warp smem ----
        #pragma unroll
        for (int j = 0; j < 8; j++) {
            float2 p0 = {s[j][0], s[j][1]};
            float2 p1 = {s[j][2], s[j][3]};
            *(float2*)&Pw[gr * APAD + j * 8 + 2 * gc] = p0;
            *(float2*)&Pw[(gr + 8) * APAD + j * 8 + 2 * gc] = p1;
        }
        __syncwarp();

        // ---- O += P V ----
        #pragma unroll
        for (int ks = 0; ks < 8; ks++) {
            uint32_t pa[4];
            pa[0] = f2tf(Pw[gr * APAD + ks * 8 + gc]);
            pa[1] = f2tf(Pw[(gr + 8) * APAD + ks * 8 + gc]);
            pa[2] = f2tf(Pw[gr * APAD + ks * 8 + gc + 4]);
            pa[3] = f2tf(Pw[(gr + 8) * APAD + ks * 8 + gc + 4]);
            #pragma unroll
            for (int j = 0; j < 8; j++) {
                uint32_t br[2];
                br[0] = f2tf(VT[(j * 8 + gr) * APAD + ks * 8 + gc]);
                br[1] = f2tf(VT[(j * 8 + gr) * APAD + ks * 8 + gc + 4]);
                mma_tf32(o[j], pa, br);
            }
        }
        __syncwarp();
    }

    // ---- normalize + store ----
    float inv0 = 1.f / l0, inv1 = 1.f / l1;
    float* Ob = O + ((size_t)b * SEQ + q0) * DMODEL + hh * DKH;
    int r0 = wrow + gr;
    #pragma unroll
    for (int j = 0; j < 8; j++) {
        int col = j * 8 + 2 * gc;
        float2 v0 = {o[j][0] * inv0, o[j][1] * inv0};
        float2 v1 = {o[j][2] * inv1, o[j][3] * inv1};
        *(float2*)&Ob[(size_t)r0 * DMODEL + col] = v0;
        *(float2*)&Ob[(size_t)(r0 + 8) * DMODEL + col] = v1;
    }
}

// ================= launch =================
extern "C" void kernel_launch(void* const* d_in, const int* in_sizes, int n_in,
                              void* d_out, int out_size) {
    const float* x    = (const float*)d_in[0];
    const int*   mask = (const int*)  d_in[1];
    const float* wq = (const float*)d_in[2];  const float* bq = (const float*)d_in[3];
    const float* wk = (const float*)d_in[4];  const float* bk = (const float*)d_in[5];
    const float* wv = (const float*)d_in[6];  const float* bv = (const float*)d_in[7];
    const float* wo = (const float*)d_in[8];  const float* bo = (const float*)d_in[9];
    const float* w1 = (const float*)d_in[10]; const float* b1 = (const float*)d_in[11];
    const float* w2 = (const float*)d_in[12]; const float* b2 = (const float*)d_in[13];
    const float* a1 = (const float*)d_in[14]; const float* g1 = (const float*)d_in[15];
    const float* a2 = (const float*)d_in[16]; const float* g2 = (const float*)d_in[17];
    float* out = (float*)d_out;

    float *h, *q, *k, *v, *ctx, *x1, *h2, *ff;
    cudaGetSymbolAddress((void**)&h,   g_h);
    cudaGetSymbolAddress((void**)&q,   g_q);
    cudaGetSymbolAddress((void**)&k,   g_k);
    cudaGetSymbolAddress((void**)&v,   g_v);
    cudaGetSymbolAddress((void**)&ctx, g_ctx);
    cudaGetSymbolAddress((void**)&x1,  g_x1);
    cudaGetSymbolAddress((void**)&h2,  g_h2);
    cudaGetSymbolAddress((void**)&ff,  g_ff);

    cudaFuncSetAttribute(gemm_mma<0,0>, cudaFuncAttributeMaxDynamicSharedMemorySize, GEMM_SMEM);
    cudaFuncSetAttribute(gemm_mma<0,1>, cudaFuncAttributeMaxDynamicSharedMemorySize, GEMM_SMEM);
    cudaFuncSetAttribute(gemm_mma<1,0>, cudaFuncAttributeMaxDynamicSharedMemorySize, GEMM_SMEM);
    cudaFuncSetAttribute(attn_mma, cudaFuncAttributeMaxDynamicSharedMemorySize, ATTN_SMEM);

    // LN1
    ln_k<<<MROWS, 128>>>(x, h, a1, g1);

    // QKV projections
    dim3 gp(DMODEL / 128, MROWS / 128);
    gemm_mma<0,0><<<gp, 256, GEMM_SMEM>>>(h, wq, bq, nullptr, q, MROWS, DMODEL, DMODEL);
    gemm_mma<0,0><<<gp, 256, GEMM_SMEM>>>(h, wk, bk, nullptr, k, MROWS, DMODEL, DMODEL);
    gemm_mma<0,0><<<gp, 256, GEMM_SMEM>>>(h, wv, bv, nullptr, v, MROWS, DMODEL, DMODEL);

    // attention (tensor cores)
    dim3 ga(NB * NH, SEQ / 128);
    attn_mma<<<ga, 256, ATTN_SMEM>>>(q, k, v, mask, ctx);

    // output projection + residual
    gemm_mma<0,1><<<gp, 256, GEMM_SMEM>>>(ctx, wo, bo, x, x1, MROWS, DMODEL, DMODEL);

    // LN2
    ln_k<<<MROWS, 128>>>(x1, h2, a2, g2);

    // FFN
    dim3 gf1(FDIM / 128, MROWS / 128);
    gemm_mma<1,0><<<gf1, 256, GEMM_SMEM>>>(h2, w1, b1, nullptr, ff, MROWS, FDIM, DMODEL);
    gemm_mma<0,1><<<gp, 256, GEMM_SMEM>>>(ff, w2, b2, x1, out, MROWS, DMODEL, FDIM);
}